// round 8
// baseline (speedup 1.0000x reference)
#include <cuda_runtime.h>
#include <cstdint>
#include <math.h>

// Problem constants
#define Bq 16
#define Nq 4096
#define Cq 81
#define MAXPC 4096   // max candidates per (b,c) AND per image (each roi emits <=1 candidate total)
#define KK 200       // per-class cap and final output count
#define NW 7         // ceil(200/32) words for keep/suppress bitmasks

#define NV4 (Bq * Nq * Cq / 4)      // 1327104 float4s
#define FTHREADS (NV4 / 8)          // 165888 threads, 8 float4s each (single wave)
#define FBLOCKS (FTHREADS / 256)    // 648 blocks

typedef unsigned long long u64;

// ---------------- device scratch (allocation-free rule: __device__ globals) ----------------
// Counters start zeroed (static init) and are re-zeroed by their consumer kernel each run,
// so every graph replay sees clean state without a dedicated zeroing launch.
__device__ int   g_cnt[Bq * Cq];                        // per-(b,c) candidate counts
__device__ float g_cscore[(size_t)Bq * Cq * MAXPC];     // per-(b,c) candidate scores
__device__ int   g_cidx[(size_t)Bq * Cq * MAXPC];       // per-(b,c) candidate roi indices
__device__ int   g_kcnt[Bq];                            // per-image kept counts
__device__ float g_kscore[Bq * MAXPC];
__device__ float g_kbox[Bq * MAXPC * 4];
__device__ int   g_ktag[Bq * MAXPC];                    // tag = class*4096 + roi_idx (<2^19)

// ---------------- kernel 1: streaming threshold filter (no argmax needed!) ----------------
// Softmax rows sum to 1 => at most one element per row exceeds 0.5, and if p > 0.5 it IS
// the row argmax. The reference emits a candidate iff p > 0.5 and class != 0 (background
// argmax is zeroed, and only scores > 0.5 survive NMS validity + final top-k zeroing).
// Single wave (no tail wave), 8 independent coalesced LDG.128s per thread (MLP=8).
__device__ __forceinline__ void emit_candidate(int e, float v) {
    int c = e % Cq;
    if (c == 0) return;                       // background
    int bn = e / Cq;
    int b = bn >> 12, n = bn & (Nq - 1);
    int bc = b * Cq + c;
    int pos = atomicAdd(&g_cnt[bc], 1);
    if (pos < MAXPC) {
        g_cscore[(size_t)bc * MAXPC + pos] = v;
        g_cidx[(size_t)bc * MAXPC + pos]   = n;
    }
}

__device__ __forceinline__ void check4(const float4& p, int base) {
    if (p.x > 0.5f) emit_candidate(base + 0, p.x);
    if (p.y > 0.5f) emit_candidate(base + 1, p.y);
    if (p.z > 0.5f) emit_candidate(base + 2, p.z);
    if (p.w > 0.5f) emit_candidate(base + 3, p.w);
}

__global__ void __launch_bounds__(256) filter_emit_kernel(const float4* __restrict__ probs4) {
    int t = blockIdx.x * blockDim.x + threadIdx.x;   // 0 .. FTHREADS-1
    float4 p[8];
    #pragma unroll
    for (int k = 0; k < 8; k++)                       // 8 independent loads, all coalesced
        p[k] = __ldg(&probs4[t + k * FTHREADS]);
    #pragma unroll
    for (int k = 0; k < 8; k++)
        check4(p[k], (t + k * FTHREADS) * 4);
}

// ---------------- box decode helper ----------------
__device__ __forceinline__ void decode_box(const float* __restrict__ roi,
                                           const float* __restrict__ deltas,
                                           int b, int c, int idx,
                                           float& oy1, float& ox1, float& oy2, float& ox2) {
    const float* r = roi + ((size_t)b * Nq + idx) * 4;
    float y1 = r[0], x1 = r[1], y2 = r[2], x2 = r[3];
    float ah = y2 - y1, aw = x2 - x1;
    float acy = y1 + 0.5f * ah, acx = x1 + 0.5f * aw;
    const float* d = deltas + (((size_t)b * Nq + idx) * Cq + c) * 4;
    float dy = d[0] * 0.1f, dx = d[1] * 0.1f;
    float dh = d[2] * 0.2f, dw = d[3] * 0.2f;
    float bh = expf(dh) * ah, bw = expf(dw) * aw;
    float bcy = dy * ah + acy, bcx = dx * aw + acx;
    oy1 = bcy - 0.5f * bh; ox1 = bcx - 0.5f * bw;
    oy2 = oy1 + bh;        ox2 = ox1 + bw;
}

// ---------------- kernel 2a: warp-per-(b,c) NMS fast path (M <= 32) ----------------
// 8 warps per block, each warp owns one (b,c). Register bitonic sort + ballot greedy NMS,
// no smem, no block barriers. Classes with M > 32 are LEFT UNTOUCHED (g_cnt not reset)
// and handled by the block-level sweep kernel below.
__global__ void __launch_bounds__(256) warp_nms_kernel(const float* __restrict__ roi,
                                                       const float* __restrict__ deltas) {
    const unsigned FULL = 0xffffffffu;
    int wid = threadIdx.x >> 5, lane = threadIdx.x & 31;
    int bc = blockIdx.x * 8 + wid;                   // grid 162 * 8 = 1296
    int b = bc / Cq, c = bc % Cq;
    int M = g_cnt[bc];
    if (M == 0 || M > 32) return;                    // M>32: block kernel's job
    if (lane == 0) g_cnt[bc] = 0;                    // reset for next graph replay

    u64 key = 0ull;
    if (lane < M) {
        float sc = g_cscore[(size_t)bc * MAXPC + lane];
        int   idx = g_cidx[(size_t)bc * MAXPC + lane];
        key = ((u64)__float_as_uint(sc) << 32) | (unsigned)(Nq - 1 - idx);
    }
    // in-register bitonic sort, descending (padding keys 0 sink to the end)
    #pragma unroll
    for (int k = 2; k <= 32; k <<= 1) {
        #pragma unroll
        for (int j = k >> 1; j > 0; j >>= 1) {
            u64 other = __shfl_xor_sync(FULL, key, j);
            bool up = ((lane & j) == 0);
            bool desc = ((lane & k) == 0);
            u64 mx = key > other ? key : other;
            u64 mn = key > other ? other : key;
            key = (desc == up) ? mx : mn;
        }
    }
    int M2 = M;   // <= 32 <= KK, per-class cap not binding

    float by1 = 0.f, bxx1 = 0.f, by2 = 0.f, bxx2 = 0.f, area = 0.f;
    if (lane < M2) {
        int idx = Nq - 1 - (int)(key & 0xFFFFFFFFull);
        decode_box(roi, deltas, b, c, idx, by1, bxx1, by2, bxx2);
        area = fmaxf(by2 - by1, 0.0f) * fmaxf(bxx2 - bxx1, 0.0f);
    }

    // greedy NMS: shfl-broadcast box i, ballot the suppressions (keep is warp-uniform)
    unsigned keep = (M2 >= 32) ? FULL : ((1u << M2) - 1u);
    for (int i = 0; i < M2 - 1; i++) {
        if ((keep >> i) & 1u) {
            float iy1 = __shfl_sync(FULL, by1, i);
            float ix1 = __shfl_sync(FULL, bxx1, i);
            float iy2 = __shfl_sync(FULL, by2, i);
            float ix2 = __shfl_sync(FULL, bxx2, i);
            float ia  = __shfl_sync(FULL, area, i);
            float yy1 = fmaxf(iy1, by1), xx1 = fmaxf(ix1, bxx1);
            float yy2 = fminf(iy2, by2), xx2 = fminf(ix2, bxx2);
            float inter = fmaxf(yy2 - yy1, 0.0f) * fmaxf(xx2 - xx1, 0.0f);
            float iou = inter / (ia + area - inter + 1e-8f);
            unsigned sup = __ballot_sync(FULL,
                (lane > i) && (lane < M2) && ((keep >> lane) & 1u) && (iou > 0.5f));
            keep &= ~sup;
        }
    }

    int nk = __popc(keep);
    int base = 0;
    if (lane == 0) base = atomicAdd(&g_kcnt[b], nk);
    base = __shfl_sync(FULL, base, 0);
    if ((lane < M2) && ((keep >> lane) & 1u)) {
        int pos = __popc(keep & ((lane == 0) ? 0u : ((1u << lane) - 1u)));
        int o = base + pos;
        int idx = Nq - 1 - (int)(key & 0xFFFFFFFFull);
        g_kscore[b * MAXPC + o] = __uint_as_float((unsigned)(key >> 32));
        g_ktag[b * MAXPC + o]   = c * Nq + idx;
        g_kbox[(b * MAXPC + o) * 4 + 0] = by1;
        g_kbox[(b * MAXPC + o) * 4 + 1] = bxx1;
        g_kbox[(b * MAXPC + o) * 4 + 2] = by2;
        g_kbox[(b * MAXPC + o) * 4 + 3] = bxx2;
    }
}

// ---------------- kernel 2b: block-level sweep for leftover classes (M > 32; rare) --------
// Identical to the proven R4 block kernel. Classes already handled have g_cnt == 0 and
// exit immediately, so this is typically a ~1us no-op sweep that guarantees correctness.
__global__ void per_class_nms_kernel(const float* __restrict__ roi,
                                     const float* __restrict__ deltas) {
    __shared__ u64 skey[MAXPC];                    // 32 KB
    __shared__ float sbox[KK * 4];
    __shared__ unsigned smask[KK * NW];            // suppression bit-matrix: row i = boxes i kills
    __shared__ unsigned skeep[NW];                 // final keep mask
    __shared__ int   s_base;

    int bc = blockIdx.x;
    int b = bc / Cq, c = bc % Cq;
    int M = g_cnt[bc];                             // every thread reads M before it is re-zeroed
    if (M > MAXPC) M = MAXPC;
    if (M == 0) return;                            // handled by warp kernel (or empty)

    int S = 32;
    while (S < M) S <<= 1;

    // key: score bits desc, tie -> lower roi index first (matches lax.top_k stability)
    for (int i = threadIdx.x; i < S; i += blockDim.x) {
        u64 key = 0ull;
        if (i < M) {
            float sc = g_cscore[(size_t)bc * MAXPC + i];
            int   idx = g_cidx[(size_t)bc * MAXPC + i];
            key = ((u64)__float_as_uint(sc) << 32) | (unsigned)(Nq - 1 - idx);
        }
        skey[i] = key;
    }
    __syncthreads();
    if (threadIdx.x == 0) g_cnt[bc] = 0;           // reset for next graph replay (post-barrier)

    for (int k = 2; k <= S; k <<= 1) {
        for (int j = k >> 1; j > 0; j >>= 1) {
            for (int i = threadIdx.x; i < S; i += blockDim.x) {
                int ixj = i ^ j;
                if (ixj > i) {
                    u64 a = skey[i], bv = skey[ixj];
                    bool sw = ((i & k) == 0) ? (a < bv) : (a > bv);
                    if (sw) { skey[i] = bv; skey[ixj] = a; }
                }
            }
            __syncthreads();
        }
    }

    int M2 = (M < KK) ? M : KK;   // reference per-class top-K cap

    // decode boxes for the capped candidate set; zero the bitmask rows
    for (int t = threadIdx.x; t < M2 * NW; t += blockDim.x) smask[t] = 0u;
    for (int t = threadIdx.x; t < M2; t += blockDim.x) {
        int idx = Nq - 1 - (int)(skey[t] & 0xFFFFFFFFull);
        float oy1, ox1, oy2, ox2;
        decode_box(roi, deltas, b, c, idx, oy1, ox1, oy2, ox2);
        sbox[t * 4 + 0] = oy1;
        sbox[t * 4 + 1] = ox1;
        sbox[t * 4 + 2] = oy2;
        sbox[t * 4 + 3] = ox2;
    }
    __syncthreads();

    // parallel IoU bit-matrix over all (i,j>i) pairs — no serial sync loop
    int npairs = M2 * M2;
    for (int t = threadIdx.x; t < npairs; t += blockDim.x) {
        int i = t / M2, j = t % M2;
        if (j > i) {
            float iy1 = sbox[i * 4 + 0], ix1 = sbox[i * 4 + 1];
            float iy2 = sbox[i * 4 + 2], ix2 = sbox[i * 4 + 3];
            float jy1 = sbox[j * 4 + 0], jx1 = sbox[j * 4 + 1];
            float jy2 = sbox[j * 4 + 2], jx2 = sbox[j * 4 + 3];
            float yy1 = fmaxf(iy1, jy1), xx1 = fmaxf(ix1, jx1);
            float yy2 = fminf(iy2, jy2), xx2 = fminf(ix2, jx2);
            float inter = fmaxf(yy2 - yy1, 0.0f) * fmaxf(xx2 - xx1, 0.0f);
            float ia = fmaxf(iy2 - iy1, 0.0f) * fmaxf(ix2 - ix1, 0.0f);
            float ja = fmaxf(jy2 - jy1, 0.0f) * fmaxf(jx2 - jx1, 0.0f);
            float iou = inter / (ia + ja - inter + 1e-8f);
            if (iou > 0.5f)
                atomicOr(&smask[i * NW + (j >> 5)], 1u << (j & 31));
        }
    }
    __syncthreads();

    // greedy scan in ONE warp: keep mask lives in lanes 0..NW-1, decision bit via shfl
    if (threadIdx.x < 32) {
        int w = threadIdx.x;
        unsigned kw = 0u;
        if (w < NW) {
            int lo = w * 32;
            int nb = M2 - lo;
            kw = (nb >= 32) ? 0xFFFFFFFFu : (nb <= 0 ? 0u : ((1u << nb) - 1u));
        }
        for (int i = 0; i < M2; i++) {
            unsigned ow = __shfl_sync(0xffffffffu, kw, i >> 5);
            if ((ow >> (i & 31)) & 1u) {
                if (w < NW) kw &= ~smask[i * NW + w];   // rows only contain bits j>i
            }
        }
        if (w < NW) skeep[w] = kw;
    }
    __syncthreads();

    // popcount-based compaction into the per-image list
    if (threadIdx.x == 0) {
        int nk = 0;
        for (int w = 0; w < NW; w++) nk += __popc(skeep[w]);
        s_base = atomicAdd(&g_kcnt[b], nk);
    }
    __syncthreads();
    int base = s_base;
    for (int t = threadIdx.x; t < M2; t += blockDim.x) {
        int tw = t >> 5, tb = t & 31;
        if ((skeep[tw] >> tb) & 1u) {
            int pos = 0;
            for (int w = 0; w < tw; w++) pos += __popc(skeep[w]);
            pos += __popc(skeep[tw] & ((tb == 0) ? 0u : ((1u << tb) - 1u)));
            int o = base + pos;
            u64 key = skey[t];
            int idx = Nq - 1 - (int)(key & 0xFFFFFFFFull);
            g_kscore[b * MAXPC + o] = __uint_as_float((unsigned)(key >> 32));
            g_ktag[b * MAXPC + o]   = c * Nq + idx;
            g_kbox[(b * MAXPC + o) * 4 + 0] = sbox[t * 4 + 0];
            g_kbox[(b * MAXPC + o) * 4 + 1] = sbox[t * 4 + 1];
            g_kbox[(b * MAXPC + o) * 4 + 2] = sbox[t * 4 + 2];
            g_kbox[(b * MAXPC + o) * 4 + 3] = sbox[t * 4 + 3];
        }
    }
}

// ---------------- kernel 3: per-image top-200 via radix-bucket select + small sort ----------------
// Scores of survivors are all in (0.5, 1.0) -> fp32 exponent is constant, so mantissa bits
// are monotone in score. 256-bucket histogram finds the 200th-largest's bucket; only keys
// in buckets >= that one are compacted and bitonic-sorted (typically a few hundred, not 4096).
__device__ __forceinline__ int score_bucket(unsigned bits) {
    unsigned d = bits - 0x3F000000u;     // (0, 0x800000] for scores in (0.5, 1.0]
    int bk = (int)(d >> 15);
    return bk > 255 ? 255 : bk;
}

__global__ void __launch_bounds__(256) finalize_kernel(float* __restrict__ out) {
    __shared__ u64 skey[MAXPC];   // 32 KB (worst case all keys in one bucket)
    __shared__ int hist[256];
    __shared__ int s_cnt, s_bsel;

    int b = blockIdx.x;
    int Mi = g_kcnt[b];
    if (Mi > MAXPC) Mi = MAXPC;

    hist[threadIdx.x] = 0;
    if (threadIdx.x == 0) { s_cnt = 0; g_kcnt[b] = 0; }   // reset for next graph replay
    __syncthreads();

    // pass 1: histogram of score buckets
    for (int i = threadIdx.x; i < Mi; i += blockDim.x) {
        unsigned bits = __float_as_uint(g_kscore[b * MAXPC + i]);
        atomicAdd(&hist[score_bucket(bits)], 1);
    }
    __syncthreads();

    // suffix scan from the top bucket: find bucket of the target-th largest score
    if (threadIdx.x == 0) {
        int target = Mi < KK ? Mi : KK;
        int cum = 0, bsel = 0;
        for (int bk = 255; bk >= 0; bk--) {
            cum += hist[bk];
            if (cum >= target) { bsel = bk; break; }
        }
        s_bsel = bsel;
    }
    __syncthreads();
    int bsel = s_bsel;

    // pass 2: compact candidate keys (score desc; tie -> class asc, roi asc via inverted tag;
    // low 12 bits carry the storage slot as payload)
    for (int i = threadIdx.x; i < Mi; i += blockDim.x) {
        unsigned bits = __float_as_uint(g_kscore[b * MAXPC + i]);
        if (score_bucket(bits) >= bsel) {
            int pos = atomicAdd(&s_cnt, 1);
            int tag = g_ktag[b * MAXPC + i];            // < 2^19
            skey[pos] = ((u64)bits << 32) |
                        ((u64)((0xFFFFFu - (unsigned)tag) & 0xFFFFFu) << 12) |
                        (u64)(unsigned)i;
        }
    }
    __syncthreads();
    int cnt = s_cnt;

    int S = 0;
    if (cnt > 0) { S = 32; while (S < cnt) S <<= 1; }
    for (int i = cnt + threadIdx.x; i < S; i += blockDim.x) skey[i] = 0ull;
    __syncthreads();

    // bitonic sort, descending (small S: usually 256-512)
    for (int k = 2; k <= S; k <<= 1) {
        for (int j = k >> 1; j > 0; j >>= 1) {
            for (int i = threadIdx.x; i < S; i += blockDim.x) {
                int ixj = i ^ j;
                if (ixj > i) {
                    u64 a = skey[i], bv = skey[ixj];
                    bool sw = ((i & k) == 0) ? (a < bv) : (a > bv);
                    if (sw) { skey[i] = bv; skey[ixj] = a; }
                }
            }
            __syncthreads();
        }
    }

    // write top-200 (boxes, labels, scores), zero-padding: covers 100% of d_out
    int vlim = cnt < KK ? cnt : KK;                 // == min(KK, Mi) since cnt >= min(KK, Mi)
    for (int t = threadIdx.x; t < KK; t += blockDim.x) {
        float bx0 = 0.f, bx1 = 0.f, bx2 = 0.f, bx3 = 0.f, lbl = 0.f, scv = 0.f;
        if (t < vlim) {
            u64 key = skey[t];
            scv = __uint_as_float((unsigned)(key >> 32));   // always > 0.5 here
            int slot = (int)(key & 0xFFFull);
            int tag = 0xFFFFF - (int)((key >> 12) & 0xFFFFFull);
            lbl = (float)(tag >> 12);                       // tag / 4096 = class
            const float* bp = &g_kbox[(b * MAXPC + slot) * 4];
            bx0 = fminf(fmaxf(bp[0], 0.0f), 1.0f);
            bx1 = fminf(fmaxf(bp[1], 0.0f), 1.0f);
            bx2 = fminf(fmaxf(bp[2], 0.0f), 1.0f);
            bx3 = fminf(fmaxf(bp[3], 0.0f), 1.0f);
        }
        float* ob = out + ((size_t)b * KK + t) * 4;
        ob[0] = bx0; ob[1] = bx1; ob[2] = bx2; ob[3] = bx3;
        out[(size_t)Bq * KK * 4 + (size_t)b * KK + t] = lbl;
        out[(size_t)Bq * KK * 4 + (size_t)Bq * KK + (size_t)b * KK + t] = scv;
    }
}

// ---------------- host launch ----------------
extern "C" void kernel_launch(void* const* d_in, const int* in_sizes, int n_in,
                              void* d_out, int out_size) {
    const float* roi = nullptr;     // B*N*4       = 262144
    const float* deltas = nullptr;  // B*N*C*4     = 21233664
    const float* probs = nullptr;   // B*N*C       = 5308416
    for (int i = 0; i < n_in; i++) {
        if (in_sizes[i] == Bq * Nq * 4)           roi    = (const float*)d_in[i];
        else if (in_sizes[i] == Bq * Nq * Cq * 4) deltas = (const float*)d_in[i];
        else if (in_sizes[i] == Bq * Nq * Cq)     probs  = (const float*)d_in[i];
    }
    float* out = (float*)d_out;

    filter_emit_kernel<<<FBLOCKS, 256>>>((const float4*)probs);
    warp_nms_kernel<<<Bq * Cq / 8, 256>>>(roi, deltas);       // fast path: M <= 32
    per_class_nms_kernel<<<Bq * Cq, 256>>>(roi, deltas);      // sweep: M > 32 (usually no-op)
    finalize_kernel<<<Bq, 256>>>(out);
}

// round 9
// speedup vs baseline: 1.0659x; 1.0659x over previous
#include <cuda_runtime.h>
#include <cstdint>
#include <math.h>

// Problem constants
#define Bq 16
#define Nq 4096
#define Cq 81
#define MAXPC 4096   // max candidates per (b,c) AND per image (each roi emits <=1 candidate total)
#define KK 200       // per-class cap and final output count
#define NW 7         // ceil(200/32) words for keep/suppress bitmasks

#define ROWS_PB 128  // rows (rois) per argmax block; 128*324B = 41472B smem, 16B-aligned tiles

typedef unsigned long long u64;

// ---------------- device scratch (allocation-free rule: __device__ globals) ----------------
// Counters start zeroed (static init) and are re-zeroed by their consumer kernel each run,
// so every graph replay sees clean state without a dedicated zeroing launch.
__device__ int   g_cnt[Bq * Cq];                        // per-(b,c) candidate counts
__device__ float g_cscore[(size_t)Bq * Cq * MAXPC];     // per-(b,c) candidate scores
__device__ int   g_cidx[(size_t)Bq * Cq * MAXPC];       // per-(b,c) candidate roi indices
__device__ int   g_kcnt[Bq];                            // per-image kept counts
__device__ float g_kscore[Bq * MAXPC];
__device__ float g_kbox[Bq * MAXPC * 4];
__device__ int   g_ktag[Bq * MAXPC];                    // tag = class*4096 + roi_idx (<2^19)

// ---------------- kernel 1: staged per-roi argmax + candidate emission (R4, measured 9.2us) ----
// Block stages 128 rows via coalesced float4 loads, then one thread scans one row from smem
// (stride 81 -> bank index lane*17+k mod 32: conflict-free). A softmax score can only exceed
// 0.5 for the argmax class, and background (argmax==0) rois are zeroed by the reference,
// so each roi emits <=1 candidate.
__global__ void __launch_bounds__(ROWS_PB) argmax_emit_kernel(const float* __restrict__ probs) {
    __shared__ float srow[ROWS_PB * Cq];   // 41472 B

    int tid = threadIdx.x;
    size_t base_elem = (size_t)blockIdx.x * ROWS_PB * Cq;

    // coalesced float4 staging: 128*81/4 = 2592 vectors
    const float4* __restrict__ src = (const float4*)(probs + base_elem);
    float4* dst = (float4*)srow;
    #pragma unroll
    for (int i = 0; i < (ROWS_PB * Cq / 4) / ROWS_PB; i++)
        dst[i * ROWS_PB + tid] = src[i * ROWS_PB + tid];
    {   // tail: 2592 = 20*128 + 32
        int i = 20 * ROWS_PB + tid;
        if (i < ROWS_PB * Cq / 4) dst[i] = src[i];
    }
    __syncthreads();

    // per-thread argmax over own row, two independent chains to cut dependent latency
    const float* r = srow + tid * Cq;
    float va = r[0]; int ia = 0;                 // covers k = 0..40
    #pragma unroll
    for (int k = 1; k <= 40; k++) {
        float pv = r[k];
        if (pv > va) { va = pv; ia = k; }        // strict > keeps lowest index
    }
    float vb = r[41]; int ib = 41;               // covers k = 41..80
    #pragma unroll
    for (int k = 42; k < Cq; k++) {
        float pv = r[k];
        if (pv > vb) { vb = pv; ib = k; }
    }
    // merge: all indices in chain a are smaller, so b wins only on strict >
    float v = va; int ix = ia;
    if (vb > va) { v = vb; ix = ib; }

    if (ix != 0 && v > 0.5f) {
        int g = blockIdx.x * ROWS_PB + tid;      // global roi id (blocks never straddle images)
        int b = g >> 12, n = g & (Nq - 1);
        int bc = b * Cq + ix;
        int pos = atomicAdd(&g_cnt[bc], 1);
        if (pos < MAXPC) {
            g_cscore[(size_t)bc * MAXPC + pos] = v;
            g_cidx[(size_t)bc * MAXPC + pos]   = n;
        }
    }
}

// ---------------- box decode helper ----------------
__device__ __forceinline__ void decode_box(const float* __restrict__ roi,
                                           const float* __restrict__ deltas,
                                           int b, int c, int idx,
                                           float& oy1, float& ox1, float& oy2, float& ox2) {
    const float* r = roi + ((size_t)b * Nq + idx) * 4;
    float y1 = r[0], x1 = r[1], y2 = r[2], x2 = r[3];
    float ah = y2 - y1, aw = x2 - x1;
    float acy = y1 + 0.5f * ah, acx = x1 + 0.5f * aw;
    const float* d = deltas + (((size_t)b * Nq + idx) * Cq + c) * 4;
    float dy = d[0] * 0.1f, dx = d[1] * 0.1f;
    float dh = d[2] * 0.2f, dw = d[3] * 0.2f;
    float bh = expf(dh) * ah, bw = expf(dw) * aw;
    float bcy = dy * ah + acy, bcx = dx * aw + acx;
    oy1 = bcy - 0.5f * bh; ox1 = bcx - 0.5f * bw;
    oy2 = oy1 + bh;        ox2 = ox1 + bw;
}

// ---------------- kernel 2: per-(b,c) NMS; warp fast path (M<=32) inside one launch ----------
__global__ void per_class_nms_kernel(const float* __restrict__ roi,
                                     const float* __restrict__ deltas) {
    __shared__ u64 skey[MAXPC];                    // 32 KB (slow path only)
    __shared__ float sbox[KK * 4];
    __shared__ unsigned smask[KK * NW];
    __shared__ unsigned skeep[NW];
    __shared__ int   s_base;

    const unsigned FULL = 0xffffffffu;
    int bc = blockIdx.x;
    int b = bc / Cq, c = bc % Cq;
    int M = g_cnt[bc];                             // every thread reads M before reset
    if (M > MAXPC) M = MAXPC;
    if (M == 0) return;                            // counter already 0

    // =============== FAST PATH: M <= 32, warp 0 only, zero block barriers ===============
    if (M <= 32) {
        if (threadIdx.x >= 32) return;             // all threads exit uniformly, no later bar
        int lane = threadIdx.x;
        if (lane == 0) g_cnt[bc] = 0;              // reset for next graph replay

        u64 key = 0ull;
        if (lane < M) {
            float sc = g_cscore[(size_t)bc * MAXPC + lane];
            int   idx = g_cidx[(size_t)bc * MAXPC + lane];
            key = ((u64)__float_as_uint(sc) << 32) | (unsigned)(Nq - 1 - idx);
        }
        // in-register bitonic sort, descending (padding keys 0 sink to the end)
        #pragma unroll
        for (int k = 2; k <= 32; k <<= 1) {
            #pragma unroll
            for (int j = k >> 1; j > 0; j >>= 1) {
                u64 other = __shfl_xor_sync(FULL, key, j);
                bool up = ((lane & j) == 0);
                bool desc = ((lane & k) == 0);
                u64 mx = key > other ? key : other;
                u64 mn = key > other ? other : key;
                key = (desc == up) ? mx : mn;
            }
        }
        int M2 = M;   // <= 32 <= KK

        float by1 = 0.f, bxx1 = 0.f, by2 = 0.f, bxx2 = 0.f, area = 0.f;
        if (lane < M2) {
            int idx = Nq - 1 - (int)(key & 0xFFFFFFFFull);
            decode_box(roi, deltas, b, c, idx, by1, bxx1, by2, bxx2);
            area = fmaxf(by2 - by1, 0.0f) * fmaxf(bxx2 - bxx1, 0.0f);
        }

        // greedy NMS: shfl-broadcast box i, ballot suppressions (keep is warp-uniform)
        unsigned keep = (M2 >= 32) ? FULL : ((1u << M2) - 1u);
        for (int i = 0; i < M2 - 1; i++) {
            if ((keep >> i) & 1u) {
                float iy1 = __shfl_sync(FULL, by1, i);
                float ix1 = __shfl_sync(FULL, bxx1, i);
                float iy2 = __shfl_sync(FULL, by2, i);
                float ix2 = __shfl_sync(FULL, bxx2, i);
                float ia  = __shfl_sync(FULL, area, i);
                float yy1 = fmaxf(iy1, by1), xx1 = fmaxf(ix1, bxx1);
                float yy2 = fminf(iy2, by2), xx2 = fminf(ix2, bxx2);
                float inter = fmaxf(yy2 - yy1, 0.0f) * fmaxf(xx2 - xx1, 0.0f);
                float iou = inter / (ia + area - inter + 1e-8f);
                unsigned sup = __ballot_sync(FULL,
                    (lane > i) && (lane < M2) && ((keep >> lane) & 1u) && (iou > 0.5f));
                keep &= ~sup;
            }
        }

        int nk = __popc(keep);
        int base = 0;
        if (lane == 0) base = atomicAdd(&g_kcnt[b], nk);
        base = __shfl_sync(FULL, base, 0);
        if ((lane < M2) && ((keep >> lane) & 1u)) {
            int pos = __popc(keep & ((lane == 0) ? 0u : ((1u << lane) - 1u)));
            int o = base + pos;
            int idx = Nq - 1 - (int)(key & 0xFFFFFFFFull);
            g_kscore[b * MAXPC + o] = __uint_as_float((unsigned)(key >> 32));
            g_ktag[b * MAXPC + o]   = c * Nq + idx;
            g_kbox[(b * MAXPC + o) * 4 + 0] = by1;
            g_kbox[(b * MAXPC + o) * 4 + 1] = bxx1;
            g_kbox[(b * MAXPC + o) * 4 + 2] = by2;
            g_kbox[(b * MAXPC + o) * 4 + 3] = bxx2;
        }
        return;
    }

    // =============== SLOW PATH: M > 32 (rare) — proven R4 block implementation ===============
    int S = 64;
    while (S < M) S <<= 1;

    for (int i = threadIdx.x; i < S; i += blockDim.x) {
        u64 key = 0ull;
        if (i < M) {
            float sc = g_cscore[(size_t)bc * MAXPC + i];
            int   idx = g_cidx[(size_t)bc * MAXPC + i];
            key = ((u64)__float_as_uint(sc) << 32) | (unsigned)(Nq - 1 - idx);
        }
        skey[i] = key;
    }
    __syncthreads();
    if (threadIdx.x == 0) g_cnt[bc] = 0;           // reset (post-barrier)

    for (int k = 2; k <= S; k <<= 1) {
        for (int j = k >> 1; j > 0; j >>= 1) {
            for (int i = threadIdx.x; i < S; i += blockDim.x) {
                int ixj = i ^ j;
                if (ixj > i) {
                    u64 a = skey[i], bv = skey[ixj];
                    bool sw = ((i & k) == 0) ? (a < bv) : (a > bv);
                    if (sw) { skey[i] = bv; skey[ixj] = a; }
                }
            }
            __syncthreads();
        }
    }

    int M2 = (M < KK) ? M : KK;   // reference per-class top-K cap

    for (int t = threadIdx.x; t < M2 * NW; t += blockDim.x) smask[t] = 0u;
    for (int t = threadIdx.x; t < M2; t += blockDim.x) {
        int idx = Nq - 1 - (int)(skey[t] & 0xFFFFFFFFull);
        float oy1, ox1, oy2, ox2;
        decode_box(roi, deltas, b, c, idx, oy1, ox1, oy2, ox2);
        sbox[t * 4 + 0] = oy1;
        sbox[t * 4 + 1] = ox1;
        sbox[t * 4 + 2] = oy2;
        sbox[t * 4 + 3] = ox2;
    }
    __syncthreads();

    int npairs = M2 * M2;
    for (int t = threadIdx.x; t < npairs; t += blockDim.x) {
        int i = t / M2, j = t % M2;
        if (j > i) {
            float iy1 = sbox[i * 4 + 0], ix1 = sbox[i * 4 + 1];
            float iy2 = sbox[i * 4 + 2], ix2 = sbox[i * 4 + 3];
            float jy1 = sbox[j * 4 + 0], jx1 = sbox[j * 4 + 1];
            float jy2 = sbox[j * 4 + 2], jx2 = sbox[j * 4 + 3];
            float yy1 = fmaxf(iy1, jy1), xx1 = fmaxf(ix1, jx1);
            float yy2 = fminf(iy2, jy2), xx2 = fminf(ix2, jx2);
            float inter = fmaxf(yy2 - yy1, 0.0f) * fmaxf(xx2 - xx1, 0.0f);
            float ia = fmaxf(iy2 - iy1, 0.0f) * fmaxf(ix2 - ix1, 0.0f);
            float ja = fmaxf(jy2 - jy1, 0.0f) * fmaxf(jx2 - jx1, 0.0f);
            float iou = inter / (ia + ja - inter + 1e-8f);
            if (iou > 0.5f)
                atomicOr(&smask[i * NW + (j >> 5)], 1u << (j & 31));
        }
    }
    __syncthreads();

    if (threadIdx.x < 32) {
        int w = threadIdx.x;
        unsigned kw = 0u;
        if (w < NW) {
            int lo = w * 32, nb = M2 - lo;
            kw = (nb >= 32) ? 0xFFFFFFFFu : (nb <= 0 ? 0u : ((1u << nb) - 1u));
        }
        for (int i = 0; i < M2; i++) {
            unsigned ow = __shfl_sync(FULL, kw, i >> 5);
            if ((ow >> (i & 31)) & 1u) {
                if (w < NW) kw &= ~smask[i * NW + w];
            }
        }
        if (w < NW) skeep[w] = kw;
    }
    __syncthreads();

    if (threadIdx.x == 0) {
        int nk = 0;
        for (int w = 0; w < NW; w++) nk += __popc(skeep[w]);
        s_base = atomicAdd(&g_kcnt[b], nk);
    }
    __syncthreads();
    int base = s_base;
    for (int t = threadIdx.x; t < M2; t += blockDim.x) {
        int tw = t >> 5, tb = t & 31;
        if ((skeep[tw] >> tb) & 1u) {
            int pos = 0;
            for (int w = 0; w < tw; w++) pos += __popc(skeep[w]);
            pos += __popc(skeep[tw] & ((tb == 0) ? 0u : ((1u << tb) - 1u)));
            int o = base + pos;
            u64 key = skey[t];
            int idx = Nq - 1 - (int)(key & 0xFFFFFFFFull);
            g_kscore[b * MAXPC + o] = __uint_as_float((unsigned)(key >> 32));
            g_ktag[b * MAXPC + o]   = c * Nq + idx;
            g_kbox[(b * MAXPC + o) * 4 + 0] = sbox[t * 4 + 0];
            g_kbox[(b * MAXPC + o) * 4 + 1] = sbox[t * 4 + 1];
            g_kbox[(b * MAXPC + o) * 4 + 2] = sbox[t * 4 + 2];
            g_kbox[(b * MAXPC + o) * 4 + 3] = sbox[t * 4 + 3];
        }
    }
}

// ---------------- kernel 3: per-image top-200 via TWO-LEVEL radix select + tiny sort ----------
// Scores cluster near 1.0 (softmax saturates), so a single 256-bucket histogram leaves
// hundreds of keys in the top bucket. Level 2 refines the cutoff bucket with the next
// 8 mantissa bits (128-ulp granularity), shrinking the sort set to ~target size.
__device__ __forceinline__ unsigned score_dd(unsigned bits) {
    unsigned d = bits - 0x3F000000u;     // (0, 0x800000] for scores in (0.5, 1.0]
    return d > 0x7FFFFFu ? 0x7FFFFFu : d;
}

__global__ void __launch_bounds__(1024) finalize_kernel(float* __restrict__ out) {
    __shared__ u64 skey[MAXPC];   // 32 KB (worst case: all keys tie at the cutoff)
    __shared__ int hist[256];
    __shared__ int s_cnt, s_bsel, s_need2, s_bsel2;

    int b = blockIdx.x;
    int Mi = g_kcnt[b];
    if (Mi > MAXPC) Mi = MAXPC;
    int target = Mi < KK ? Mi : KK;

    if (threadIdx.x < 256) hist[threadIdx.x] = 0;
    if (threadIdx.x == 0) { s_cnt = 0; g_kcnt[b] = 0; }   // reset for next graph replay
    __syncthreads();

    // level-1 histogram: top 8 bits of mantissa-delta
    for (int i = threadIdx.x; i < Mi; i += blockDim.x) {
        unsigned dd = score_dd(__float_as_uint(g_kscore[b * MAXPC + i]));
        atomicAdd(&hist[dd >> 15], 1);
    }
    __syncthreads();

    if (threadIdx.x == 0) {
        int cum = 0, bsel = 0;
        for (int bk = 255; bk >= 0; bk--) {
            cum += hist[bk];
            if (cum >= target) {
                bsel = bk;
                s_need2 = target - (cum - hist[bk]);   // how many we still need from bucket bsel
                break;
            }
        }
        s_bsel = bsel;
    }
    __syncthreads();
    int bsel = s_bsel, need2 = s_need2;

    // level-2 histogram within the cutoff bucket: next 8 bits
    if (threadIdx.x < 256) hist[threadIdx.x] = 0;
    __syncthreads();
    for (int i = threadIdx.x; i < Mi; i += blockDim.x) {
        unsigned dd = score_dd(__float_as_uint(g_kscore[b * MAXPC + i]));
        if ((int)(dd >> 15) == bsel)
            atomicAdd(&hist[(dd >> 7) & 0xFF], 1);
    }
    __syncthreads();

    if (threadIdx.x == 0) {
        int cum = 0, bsel2 = 0;
        for (int bk = 255; bk >= 0; bk--) {
            cum += hist[bk];
            if (cum >= need2) { bsel2 = bk; break; }
        }
        s_bsel2 = bsel2;
    }
    __syncthreads();
    int bsel2 = s_bsel2;

    // compact keys above the refined cutoff (score desc; tie -> class asc, roi asc via
    // inverted tag; low 12 bits carry the storage slot as payload)
    for (int i = threadIdx.x; i < Mi; i += blockDim.x) {
        unsigned bits = __float_as_uint(g_kscore[b * MAXPC + i]);
        unsigned dd = score_dd(bits);
        int l1 = (int)(dd >> 15);
        bool take = (l1 > bsel) || (l1 == bsel && (int)((dd >> 7) & 0xFF) >= bsel2);
        if (take) {
            int pos = atomicAdd(&s_cnt, 1);
            int tag = g_ktag[b * MAXPC + i];            // < 2^19
            skey[pos] = ((u64)bits << 32) |
                        ((u64)((0xFFFFFu - (unsigned)tag) & 0xFFFFFu) << 12) |
                        (u64)(unsigned)i;
        }
    }
    __syncthreads();
    int cnt = s_cnt;                                    // ~target + few (128-ulp ties)

    int S = 0;
    if (cnt > 0) { S = 32; while (S < cnt) S <<= 1; }
    for (int i = cnt + threadIdx.x; i < S; i += blockDim.x) skey[i] = 0ull;
    __syncthreads();

    // bitonic sort, descending (S typically 256)
    for (int k = 2; k <= S; k <<= 1) {
        for (int j = k >> 1; j > 0; j >>= 1) {
            for (int i = threadIdx.x; i < S; i += blockDim.x) {
                int ixj = i ^ j;
                if (ixj > i) {
                    u64 a = skey[i], bv = skey[ixj];
                    bool sw = ((i & k) == 0) ? (a < bv) : (a > bv);
                    if (sw) { skey[i] = bv; skey[ixj] = a; }
                }
            }
            __syncthreads();
        }
    }

    // write top-200 (boxes, labels, scores), zero-padding: covers 100% of d_out
    int vlim = cnt < target ? cnt : target;             // cnt >= target by construction
    for (int t = threadIdx.x; t < KK; t += blockDim.x) {
        float bx0 = 0.f, bx1 = 0.f, bx2 = 0.f, bx3 = 0.f, lbl = 0.f, scv = 0.f;
        if (t < vlim) {
            u64 key = skey[t];
            scv = __uint_as_float((unsigned)(key >> 32));   // always > 0.5 here
            int slot = (int)(key & 0xFFFull);
            int tag = 0xFFFFF - (int)((key >> 12) & 0xFFFFFull);
            lbl = (float)(tag >> 12);                       // tag / 4096 = class
            const float* bp = &g_kbox[(b * MAXPC + slot) * 4];
            bx0 = fminf(fmaxf(bp[0], 0.0f), 1.0f);
            bx1 = fminf(fmaxf(bp[1], 0.0f), 1.0f);
            bx2 = fminf(fmaxf(bp[2], 0.0f), 1.0f);
            bx3 = fminf(fmaxf(bp[3], 0.0f), 1.0f);
        }
        float* ob = out + ((size_t)b * KK + t) * 4;
        ob[0] = bx0; ob[1] = bx1; ob[2] = bx2; ob[3] = bx3;
        out[(size_t)Bq * KK * 4 + (size_t)b * KK + t] = lbl;
        out[(size_t)Bq * KK * 4 + (size_t)Bq * KK + (size_t)b * KK + t] = scv;
    }
}

// ---------------- host launch ----------------
extern "C" void kernel_launch(void* const* d_in, const int* in_sizes, int n_in,
                              void* d_out, int out_size) {
    const float* roi = nullptr;     // B*N*4       = 262144
    const float* deltas = nullptr;  // B*N*C*4     = 21233664
    const float* probs = nullptr;   // B*N*C       = 5308416
    for (int i = 0; i < n_in; i++) {
        if (in_sizes[i] == Bq * Nq * 4)           roi    = (const float*)d_in[i];
        else if (in_sizes[i] == Bq * Nq * Cq * 4) deltas = (const float*)d_in[i];
        else if (in_sizes[i] == Bq * Nq * Cq)     probs  = (const float*)d_in[i];
    }
    float* out = (float*)d_out;

    argmax_emit_kernel<<<(Bq * Nq) / ROWS_PB, ROWS_PB>>>(probs);
    per_class_nms_kernel<<<Bq * Cq, 256>>>(roi, deltas);
    finalize_kernel<<<Bq, 1024>>>(out);
}